// round 17
// baseline (speedup 1.0000x reference)
#include <cuda_runtime.h>
#include <cuda_bf16.h>
#include <cstdint>

// ---------------------------------------------------------------------------
// BertAttention (DeBERTa) — round 17: V-projection overlapped with tables
// (tables don't need V). B=1, S=2048, H=768, NH=12, D=64, SPAN=512
// ---------------------------------------------------------------------------

constexpr int S    = 2048;
constexpr int H    = 768;
constexpr int NH   = 12;
constexpr int D    = 64;
constexpr int LPOS = 1024;  // 2*SPAN
constexpr int ZSPL = 4;     // split-K factor over key sequence
constexpr float SCALE2 = 0.07216878364870322f * 1.4426950408889634f;
constexpr float NEGMAX = -3.402823466e38f;

using bf16 = __nv_bfloat16;

// ---------------------------- scratch (device globals) ---------------------
__device__ bf16   g_hbf  [S * H];
__device__ bf16   g_relbf[LPOS * H];
__device__ bf16   g_Wt   [6 * H * H];
__device__ bf16   g_Qbf  [S * H];
__device__ bf16   g_Kbf  [S * H];
__device__ bf16   g_Vt   [H * S];
__device__ bf16   g_PKbf [LPOS * H];
__device__ bf16   g_PQbf [LPOS * H];
__device__ bf16   g_CKb  [(size_t)NH * S * LPOS];
__device__ bf16   g_CQb  [(size_t)NH * S * LPOS + 256];
__device__ float  g_Opart[(size_t)ZSPL * NH * S * D];
__device__ float2 g_ML   [ZSPL * NH * S];
__device__ bf16   g_CTXbf[S * H];
__device__ float  g_TMP  [S * H];

// ---------------------------- PTX helpers ----------------------------------
__device__ __forceinline__ uint32_t smem_u32(const void* p) {
    uint32_t a;
    asm("{ .reg .u64 t; cvta.to.shared.u64 t, %1; cvt.u32.u64 %0, t; }"
        : "=r"(a) : "l"(p));
    return a;
}
__device__ __forceinline__ void cpasync16(uint32_t dst, const void* src) {
    asm volatile("cp.async.cg.shared.global [%0], [%1], 16;" :: "r"(dst), "l"(src));
}
#define CP_COMMIT() asm volatile("cp.async.commit_group;" ::: "memory")
#define CP_WAIT1()  asm volatile("cp.async.wait_group 1;" ::: "memory")
#define CP_WAIT0()  asm volatile("cp.async.wait_group 0;" ::: "memory")

__device__ __forceinline__ void ldsm4(uint32_t* r, uint32_t addr) {
    asm volatile("ldmatrix.sync.aligned.m8n8.x4.shared.b16 {%0,%1,%2,%3}, [%4];"
                 : "=r"(r[0]), "=r"(r[1]), "=r"(r[2]), "=r"(r[3]) : "r"(addr));
}
__device__ __forceinline__ void mma16816(float* c, const uint32_t* a, const uint32_t* b) {
    asm volatile(
        "mma.sync.aligned.m16n8k16.row.col.f32.bf16.bf16.f32 "
        "{%0,%1,%2,%3}, {%4,%5,%6,%7}, {%8,%9}, {%0,%1,%2,%3};"
        : "+f"(c[0]), "+f"(c[1]), "+f"(c[2]), "+f"(c[3])
        : "r"(a[0]), "r"(a[1]), "r"(a[2]), "r"(a[3]), "r"(b[0]), "r"(b[1]));
}
__device__ __forceinline__ uint32_t packbf2(float a, float b) {
    __nv_bfloat162 t = __float22bfloat162_rn(make_float2(a, b));
    return *(uint32_t*)&t;
}

__device__ __forceinline__ uint32_t swz(int row, int chunk) {
    return (uint32_t)(row * 64 + ((chunk ^ ((row >> 1) & 3)) << 4));
}
__device__ __forceinline__ uint32_t swz128(int row, int c16) {
    return (uint32_t)(row * 128 + ((c16 ^ (row & 7)) << 4));
}

// ---------------------------------------------------------------------------
// Shared GEMM mainloop (128x128 tile, K-major bf16, NT).
// ---------------------------------------------------------------------------
struct SmemPtrs { uint32_t uA, uB; };

template<typename LoadFn>
__device__ __forceinline__ void gemm_core(
    int nch, SmemPtrs sp, int tid, int lane, int wm, int wn,
    float (&acc)[4][4][4], LoadFn load_tiles)
{
    constexpr int ABYTES = 128 * 32 * 2;
    constexpr int BBYTES = 128 * 32 * 2;
    load_tiles(0, 0);
    CP_COMMIT();
    for (int ch = 0; ch < nch; ch++) {
        const int st = ch & 1;
        if (ch + 1 < nch) { load_tiles(ch + 1, st ^ 1); CP_COMMIT(); CP_WAIT1(); }
        else              { CP_WAIT0(); }
        __syncthreads();
        const uint32_t bA = sp.uA + st * ABYTES;
        const uint32_t bB = sp.uB + st * BBYTES;
        #pragma unroll
        for (int kk = 0; kk < 2; kk++) {
            uint32_t afr[4][4];
            #pragma unroll
            for (int i = 0; i < 4; i++) {
                int row = wm * 64 + i * 16 + (lane & 15);
                int chk = kk * 2 + (lane >> 4);
                ldsm4(afr[i], bA + swz(row, chk));
            }
            uint32_t bfr[4][2];
            #pragma unroll
            for (int p = 0; p < 2; p++) {
                uint32_t r4[4];
                int n   = wn * 32 + p * 16 + ((lane >> 4) << 3) + (lane & 7);
                int chk = kk * 2 + ((lane >> 3) & 1);
                ldsm4(r4, bB + swz(n, chk));
                bfr[2 * p][0] = r4[0]; bfr[2 * p][1] = r4[1];
                bfr[2 * p + 1][0] = r4[2]; bfr[2 * p + 1][1] = r4[3];
            }
            #pragma unroll
            for (int i = 0; i < 4; i++)
                #pragma unroll
                for (int j = 0; j < 4; j++)
                    mma16816(acc[i][j], afr[i], bfr[j]);
        }
        __syncthreads();
    }
}

// ---------------------------------------------------------------------------
// Fused projection kernel: up to 5 jobs in one 1-D grid.
// ---------------------------------------------------------------------------
struct ProjJobs {
    const bf16* A[5];
    const bf16* Bw[5];
    bf16*       C[5];
    const float* bias[5];
    int mode[5];
    int start[6];
};

__global__ void __launch_bounds__(256) gemm_proj(ProjJobs J)
{
    constexpr int ABYTES = 128 * 32 * 2, BBYTES = 128 * 32 * 2;
    __shared__ __align__(1024) char sm[2 * (ABYTES + BBYTES)];
    SmemPtrs sp { smem_u32(sm), smem_u32(sm) + 2 * ABYTES };

    int bx = blockIdx.x;
    int j = 0;
    while (bx >= J.start[j + 1]) j++;
    const int local = bx - J.start[j];
    const int bm = (local / 6) * 128, bn = (local % 6) * 128;

    const int tid = threadIdx.x, lane = tid & 31, wid = tid >> 5;
    const int wm = wid & 1, wn = wid >> 1;

    const bf16* Arow = J.A[j] + (long)bm * H;
    const bf16* Brow = J.Bw[j] + (long)bn * H;

    auto load_tiles = [&](int ch, int st) {
        const bf16* Ak = Arow + ch * 32;
        #pragma unroll
        for (int i = tid; i < 512; i += 256) {
            int r = i >> 2, c = i & 3;
            cpasync16(sp.uA + st * ABYTES + swz(r, c), Ak + (long)r * H + c * 8);
        }
        const bf16* Bk = Brow + ch * 32;
        #pragma unroll
        for (int i = tid; i < 512; i += 256) {
            int r = i >> 2, c = i & 3;
            cpasync16(sp.uB + st * BBYTES + swz(r, c), Bk + (long)r * H + c * 8);
        }
    };

    float acc[4][4][4] = {};
    gemm_core(H / 32, sp, tid, lane, wm, wn, acc, load_tiles);

    bf16* C = J.C[j];
    const float* bias = J.bias[j];
    const int mode = J.mode[j];

    #pragma unroll
    for (int i = 0; i < 4; i++)
        #pragma unroll
        for (int jj = 0; jj < 4; jj++)
            #pragma unroll
            for (int half = 0; half < 2; half++) {
                const int r = bm + wm * 64 + i * 16 + (lane >> 2) + half * 8;
                const int c = bn + wn * 32 + jj * 8 + (lane & 3) * 2;
                const float v0 = acc[i][jj][half * 2];
                const float v1 = acc[i][jj][half * 2 + 1];
                float b0 = bias ? bias[c] : 0.f, b1 = bias ? bias[c + 1] : 0.f;
                if (mode == 0) {
                    *(__nv_bfloat162*)(C + (long)r * H + c) =
                        __float22bfloat162_rn(make_float2(v0 + b0, v1 + b1));
                } else {
                    C[(long)c * S + r]       = __float2bfloat16(v0 + b0);
                    C[(long)(c + 1) * S + r] = __float2bfloat16(v1 + b1);
                }
            }
}

// ---------------------------------------------------------------------------
// Single-shot tables kernel (K=64 fits one smem load, no pipeline).
// ---------------------------------------------------------------------------
constexpr int TB_STRIDE = 272;

__global__ void __launch_bounds__(256) gemm_tables(
    const bf16* __restrict__ Qb, const bf16* __restrict__ Kb,
    const bf16* __restrict__ PK, const bf16* __restrict__ PQ,
    bf16* __restrict__ CK, bf16* __restrict__ CQ, int hbase)
{
    __shared__ __align__(1024) char sm[128 * TB_STRIDE];
    const uint32_t uA = smem_u32(sm);
    const uint32_t uB = uA + 16384;

    const int z = blockIdx.z;
    const bool isCK = z < 6;
    const int h = hbase + (isCK ? z : z - 6);
    const bf16* A = (isCK ? Qb : Kb) + h * D;
    const bf16* B = (isCK ? PK : PQ) + h * D;
    bf16* C = (isCK ? CK : CQ) + (size_t)h * S * LPOS;

    const int tid = threadIdx.x, lane = tid & 31, wid = tid >> 5;
    const int wm = wid & 1, wn = wid >> 1;
    const int bm = blockIdx.y * 128, bn = blockIdx.x * 128;

    {
        const bf16* Ag = A + (long)bm * H;
        #pragma unroll
        for (int i = tid; i < 1024; i += 256) {
            int r = i >> 3, c = i & 7;
            cpasync16(uA + swz128(r, c), Ag + (long)r * H + c * 8);
        }
        const bf16* Bg = B + (long)bn * H;
        #pragma unroll
        for (int i = tid; i < 1024; i += 256) {
            int r = i >> 3, c = i & 7;
            cpasync16(uB + swz128(r, c), Bg + (long)r * H + c * 8);
        }
    }
    CP_COMMIT();
    CP_WAIT0();
    __syncthreads();

    float acc[4][4][4] = {};
    #pragma unroll
    for (int kk = 0; kk < 4; kk++) {
        uint32_t afr[4][4];
        #pragma unroll
        for (int i = 0; i < 4; i++) {
            int row = wm * 64 + i * 16 + (lane & 15);
            int c16 = kk * 2 + (lane >> 4);
            ldsm4(afr[i], uA + swz128(row, c16));
        }
        uint32_t bfr[4][2];
        #pragma unroll
        for (int p = 0; p < 2; p++) {
            uint32_t r4[4];
            int n   = wn * 32 + p * 16 + ((lane >> 4) << 3) + (lane & 7);
            int c16 = kk * 2 + ((lane >> 3) & 1);
            ldsm4(r4, uB + swz128(n, c16));
            bfr[2 * p][0] = r4[0]; bfr[2 * p][1] = r4[1];
            bfr[2 * p + 1][0] = r4[2]; bfr[2 * p + 1][1] = r4[3];
        }
        #pragma unroll
        for (int i = 0; i < 4; i++)
            #pragma unroll
            for (int j = 0; j < 4; j++)
                mma16816(acc[i][j], afr[i], bfr[j]);
    }
    __syncthreads();

    #pragma unroll
    for (int i = 0; i < 4; i++)
        #pragma unroll
        for (int jj = 0; jj < 4; jj++)
            #pragma unroll
            for (int half = 0; half < 2; half++) {
                const int rl = wm * 64 + i * 16 + (lane >> 2) + half * 8;
                const int cl = wn * 32 + jj * 8 + (lane & 3) * 2;
                *(uint32_t*)(sm + rl * TB_STRIDE + cl * 2) =
                    packbf2(acc[i][jj][half * 2], acc[i][jj][half * 2 + 1]);
            }
    __syncthreads();

    #pragma unroll
    for (int i = tid; i < 2048; i += 256) {
        int r = i >> 4, ch = i & 15;
        uint4 v = *(uint4*)(sm + r * TB_STRIDE + ch * 16);
        *(uint4*)(C + (long)(bm + r) * LPOS + bn + ch * 8) = v;
    }
}

// ---------------------------------------------------------------------------
// Output projection + bias + residual (fp32 out).
// ---------------------------------------------------------------------------
__global__ void __launch_bounds__(256) gemm_out(
    const bf16* __restrict__ A, const bf16* __restrict__ Bw,
    float* __restrict__ C, const float* __restrict__ bias,
    const float* __restrict__ res)
{
    constexpr int ABYTES = 128 * 32 * 2, BBYTES = 128 * 32 * 2;
    __shared__ __align__(1024) char sm[2 * (ABYTES + BBYTES)];
    SmemPtrs sp { smem_u32(sm), smem_u32(sm) + 2 * ABYTES };

    const int tid = threadIdx.x, lane = tid & 31, wid = tid >> 5;
    const int wm = wid & 1, wn = wid >> 1;
    const int bm = blockIdx.y * 128, bn = blockIdx.x * 128;

    const bf16* Arow = A + (long)bm * H;
    const bf16* Brow = Bw + (long)bn * H;

    auto load_tiles = [&](int ch, int st) {
        const bf16* Ak = Arow + ch * 32;
        #pragma unroll
        for (int i = tid; i < 512; i += 256) {
            int r = i >> 2, c = i & 3;
            cpasync16(sp.uA + st * ABYTES + swz(r, c), Ak + (long)r * H + c * 8);
        }
        const bf16* Bk = Brow + ch * 32;
        #pragma unroll
        for (int i = tid; i < 512; i += 256) {
            int r = i >> 2, c = i & 3;
            cpasync16(sp.uB + st * BBYTES + swz(r, c), Bk + (long)r * H + c * 8);
        }
    };

    float acc[4][4][4] = {};
    gemm_core(H / 32, sp, tid, lane, wm, wn, acc, load_tiles);

    #pragma unroll
    for (int i = 0; i < 4; i++)
        #pragma unroll
        for (int jj = 0; jj < 4; jj++)
            #pragma unroll
            for (int half = 0; half < 2; half++) {
                const int r = bm + wm * 64 + i * 16 + (lane >> 2) + half * 8;
                const int c = bn + wn * 32 + jj * 8 + (lane & 3) * 2;
                const float* rr = res + (long)r * H;
                *(float2*)(C + (long)r * H + c) =
                    make_float2(acc[i][jj][half * 2] + bias[c] + rr[c],
                                acc[i][jj][half * 2 + 1] + bias[c + 1] + rr[c + 1]);
            }
}

// ---------------------------------------------------------------------------
// Flash-fused attention: fast/saturated/general paths, mask bit-packed.
// ---------------------------------------------------------------------------
constexpr int CQ_W     = 144;
constexpr int CQ_ROWB  = CQ_W * 2;
constexpr int CQ_BYTES = 64 * CQ_ROWB;
constexpr int CK_W     = 80;
constexpr int CK_ROWB  = CK_W * 2;
constexpr int CK_BYTES = 128 * CK_ROWB;
constexpr int OFF_K    = 16384;
constexpr int OFF_V    = OFF_K + 16384;
constexpr int OFF_CQ   = OFF_V + 16384;
constexpr int OFF_CK   = OFF_CQ + CQ_BYTES;
constexpr int OFF_SAT  = OFF_CK + CK_BYTES;
constexpr int FL_SMEM  = OFF_SAT + 2048;      // 90112
constexpr int HTILES   = (S / 64) / ZSPL;     // 8

__global__ void __launch_bounds__(256, 2) flash_attn(
    const bf16* __restrict__ Q, const bf16* __restrict__ K,
    const bf16* __restrict__ Vt,
    const bf16* __restrict__ CKb, const bf16* __restrict__ CQb,
    const int* __restrict__ mask,
    float* __restrict__ Opart, float2* __restrict__ ML, int hbase)
{
    extern __shared__ __align__(1024) char dyn[];
    const uint32_t uQ  = smem_u32(dyn);
    const uint32_t uK  = uQ + OFF_K;
    const uint32_t uV  = uQ + OFF_V;
    const uint32_t uCQ = uQ + OFF_CQ;
    const uint32_t uCK = uQ + OFF_CK;

    const int tid = threadIdx.x, lane = tid & 31, wid = tid >> 5;
    const int h = hbase + blockIdx.y, bm = blockIdx.x * 128;
    const int z = blockIdx.z;
    const int ct0 = z * HTILES;
    const int bmc = bm + 512;

    auto lbc = [&](int c) { return min(max(bmc - c, 0), 888) & ~7; };
    auto tile_fast = [&](int dRC) { return (dRC >= -448) && (dRC <= 320); };
    auto tile_sat  = [&](int dRC) { return (dRC >= 576) || (dRC <= -640); };

    {
        const bf16* Qg = Q + (long)bm * H + h * D;
        #pragma unroll
        for (int i = tid; i < 1024; i += 256) {
            int r = i >> 3, c = i & 7;
            cpasync16(uQ + swz128(r, c), Qg + (long)r * H + c * 8);
        }
    }
    CP_COMMIT();

    auto load_kv = [&](int ct, int st) {
        const int c0 = ct * 64;
        const uint32_t uk = uK + st * 8192;
        const uint32_t uv = uV + st * 8192;
        const bf16* Kg = K + (long)c0 * H + h * D;
        #pragma unroll
        for (int i = tid; i < 512; i += 256) {
            int r = i >> 3, c = i & 7;
            cpasync16(uk + swz128(r, c), Kg + (long)r * H + c * 8);
        }
        const bf16* Vg = Vt + (long)(h * D) * S + c0;
        #pragma unroll
        for (int i = tid; i < 512; i += 256) {
            int d = i >> 3, c = i & 7;
            cpasync16(uv + swz128(d, c), Vg + (long)d * S + c * 8);
        }
    };

    auto load_band = [&](int ct) {
        const int c0 = ct * 64;
        const int dRC = bm - c0;
        if (tile_sat(dRC)) return;
        const bf16* CQg = CQb + ((size_t)h * S + c0) * LPOS;
        for (int i = tid; i < 64 * 18; i += 256) {
            int j = i / 18, ch = i % 18;
            int Lb = lbc(c0 + j);
            cpasync16(uCQ + j * CQ_ROWB + ch * 16,
                      CQg + (size_t)j * LPOS + Lb + ch * 8);
        }
        if (tile_fast(dRC)) {
            const bf16* CKg = CKb + ((size_t)h * S + bm) * LPOS;
            for (int i = tid; i < 128 * 9; i += 256) {
                int rb = i / 9, ch = i % 9;
                int Bal = (rb + dRC + 448) & ~7;
                cpasync16(uCK + rb * CK_ROWB + ch * 16,
                          CKg + (size_t)rb * LPOS + Bal + ch * 8);
            }
        }
    };

    load_kv(ct0, 0);
    CP_COMMIT();
    CP_WAIT1();
    __syncthreads();

    // one-time: saturated cq column values for this key slice
    {
        const bf16* CQg = CQb + ((size_t)h * S + ct0 * 64) * LPOS;
        bf16* slo = (bf16*)(dyn + OFF_SAT);
        bf16* shi = slo + 512;
        for (int j = tid; j < 512; j += 256) {
            slo[j] = CQg[(size_t)j * LPOS];
            shi[j] = CQg[(size_t)j * LPOS + 1023];
        }
    }

    uint32_t qf[4][4];
    #pragma unroll
    for (int kk = 0; kk < 4; kk++) {
        int row = wid * 16 + (lane & 15);
        int c16 = kk * 2 + (lane >> 4);
        ldsm4(qf[kk], uQ + swz128(row, c16));
    }

    const int rb0 = wid * 16 + (lane >> 2);
    const int rb1 = rb0 + 8;
    const int r0 = bm + rb0;
    const int r1 = bm + rb1;
    const int m0v = mask[r0], m1v = mask[r1];
    const bf16* ck0 = CKb + ((size_t)h * S + r0) * LPOS;
    const bf16* ck1 = CKb + ((size_t)h * S + r1) * LPOS;
    const float cklo0 = __bfloat162float(ck0[0]);
    const float ckhi0 = __bfloat162float(ck0[1023]);
    const float cklo1 = __bfloat162float(ck1[0]);
    const float ckhi1 = __bfloat162float(ck1[1023]);

    // pack this thread's 128 mask bits for the whole slice
    uint32_t mbits[4] = {0, 0, 0, 0};
    {
        const int cb = (lane & 3) * 2;
        #pragma unroll
        for (int it = 0; it < 8; it++)
            #pragma unroll
            for (int nb = 0; nb < 8; nb++) {
                int c = (ct0 + it) * 64 + nb * 8 + cb;
                int k = it * 16 + nb * 2;
                uint32_t b = (mask[c] ? 1u : 0u) | ((mask[c + 1] ? 2u : 0u));
                mbits[k >> 5] |= b << (k & 31);
            }
    }

    float m0 = NEGMAX, m1 = NEGMAX, l0 = 0.f, l1 = 0.f;
    float O[8][4] = {};

    for (int it = 0; it < HTILES; it++) {
        const int ct = ct0 + it;
        const int st = it & 1;

        load_band(ct);
        CP_COMMIT();
        if (it + 1 < HTILES) { load_kv(ct + 1, st ^ 1); CP_COMMIT(); CP_WAIT1(); }
        else                 { CP_WAIT0(); }
        __syncthreads();

        const uint32_t uk = uK + st * 8192;
        const uint32_t uv = uV + st * 8192;
        const bf16* sCQ = (const bf16*)(dyn + OFF_CQ);
        const bf16* sCK = (const bf16*)(dyn + OFF_CK);

        float sfr[8][4] = {};
        #pragma unroll
        for (int g = 0; g < 4; g++) {
            #pragma unroll
            for (int kk = 0; kk < 4; kk++) {
                uint32_t r4[4];
                int n   = g * 16 + ((lane >> 4) << 3) + (lane & 7);
                int c16 = kk * 2 + ((lane >> 3) & 1);
                ldsm4(r4, uk + swz128(n, c16));
                mma16816(sfr[2 * g],     qf[kk], r4);
                mma16816(sfr[2 * g + 1], qf[kk], r4 + 2);
            }
        }

        const int c0 = ct * 64;
        const int dRC = bm - c0;
        const uint32_t mw = mbits[it >> 1] >> ((it & 1) * 16);
        float tmx0 = NEGMAX, tmx1 = NEGMAX;

        if (tile_fast(dRC)) {
            const int ph = (rb0 + dRC + 448) & 7;
            const bf16* sk0 = sCK + rb0 * CK_W;
            const bf16* sk1 = sCK + rb1 * CK_W;
            #pragma unroll
            for (int nb = 0; nb < 8; nb++) {
                const int cl  = nb * 8 + (lane & 3) * 2;
                const int off = 64 - cl + ph;
                const int mc0 = (mw >> (nb * 2)) & 1;
                const int mc1 = (mw >> (nb * 2 + 1)) & 1;
                const bf16* sq0 = sCQ + cl * CQ_W;
                const bf16* sq1 = sCQ + (cl + 1) * CQ_W;
                const int q0 = dRC + 512 - cl;
                const int t0 = q0 & 7, t1 = (q0 - 1) & 7;
                {
                    float v0 = (sfr[nb][0] + __bfloat162float(sk0[off])
                                + __bfloat162float(sq0[rb0 + t0])) * SCALE2;
                    float v1 = (sfr[nb][1] + __bfloat162float(sk0[off - 1])
                                + __bfloat162float(sq1[rb0 + t1])) * SCALE2;
                    if (!(m0v && mc0)) v0 = NEGMAX;
                    if (!(m0v && mc1)) v1 = NEGMAX;
                    sfr[nb][0] = v0; sfr[nb][1] = v1;
                    tmx0 = fmaxf(tmx0, fmaxf(v0, v1));
                }
                {
                    float v2 = (sfr[nb][2] + __bfloat162float(sk1[off])
                                + __bfloat162float(sq0[rb1 + t0])) * SCALE2;
                    float v3 = (sfr[nb][3] + __bfloat162float(sk1[off - 1])
                                + __bfloat162float(sq1[rb1 + t1])) * SCALE2;
                    if (!(m1v && mc0)) v2 = NEGMAX;
                    if (!(m1v && mc1)) v3 = NEGMAX;
                    sfr[nb][2] = v2; sfr[nb][3] = v3;
                    tmx1 = fmaxf(tmx1, fmaxf(v2, v3));
                }
            }
        } else if (tile_sat(dRC)) {
            const bool hiSat = dRC > 0;
            const float f0 = hiSat ? ckhi0 : cklo0;
            const float f1 = hiSat ? ckhi1 : cklo1;
            const bf16* scq = (const bf16*)(dyn + OFF_SAT) + (hiSat ? 512 : 0);
            const int jb = it * 64;
            #pragma unroll
            for (int nb = 0; nb < 8; nb++) {
                const int cl  = nb * 8 + (lane & 3) * 2;
                const int mc0 = (mw >> (nb * 2)) & 1;
                const int mc1 = (mw >> (nb * 2 + 1)) & 1;
                const float cq0 = __bfloat162float(scq[jb + cl]);
                const float cq1 = __bfloat162float(scq[jb + cl + 1]);
                {
                    float v0 = (sfr[nb][0] + f0 + cq0) * SCALE2;
                    float v1 = (sfr[nb][1] + f0 + cq1) * SCALE2;
                    if (!(m0v && mc0)) v0 = NEGMAX;
                    if (!(m0v && mc1)) v1 = NEGMAX;
                    sfr[nb][0] = v0; sfr[nb][1] = v1;
                    tmx0 = fmaxf(tmx0, fmaxf(v0, v1));
                }
                {
                    float v2 = (sfr[nb][2] + f1 + cq0) * SCALE2;
                    float v3 = (sfr[nb][3] + f1 + cq1) * SCALE2;
                    if (!(m1v && mc0)) v2 = NEGMAX;
                    if (!(m1v && mc1)) v3 = NEGMAX;
                    sfr[nb][2] = v2; sfr[nb][3] = v3;
                    tmx1 = fmaxf(tmx1, fmaxf(v2, v3));
                }
            }
        } else {
            #pragma unroll
            for (int nb = 0; nb < 8; nb++) {
                const int cl = nb * 8 + (lane & 3) * 2;
                const int c  = c0 + cl;
                const int Lb0 = lbc(c);
                const int Lb1 = lbc(c + 1);
                const int mc0 = (mw >> (nb * 2)) & 1;
                const int mc1 = (mw >> (nb * 2 + 1)) & 1;
                {
                    int la = min(max(r0 - c + 512, 0), LPOS - 1);
                    int lb = min(max(r0 - c + 511, 0), LPOS - 1);
                    float v0 = (sfr[nb][0] + __bfloat162float(ck0[la])
                                + __bfloat162float(sCQ[cl * CQ_W + (la - Lb0)])) * SCALE2;
                    float v1 = (sfr[nb][1] + __bfloat162float(ck0[lb])
                                + __bfloat162float(sCQ[(cl + 1) * CQ_W + (lb - Lb1)])) * SCALE2;
                    if (!(m0v && mc0)) v0 = NEGMAX;
                    if (!(m0v && mc1)) v1 = NEGMAX;
                    sfr[nb][0] = v0; sfr[nb][1] = v1;
                    tmx0 = fmaxf(tmx0, fmaxf(v0, v1));
                }
                {
                    int la = min(max(r1 - c + 512, 0), LPOS - 1);
                    int lb = min(max(r1 - c + 511, 0), LPOS - 1);
                    float v2 = (sfr[nb][2] + __bfloat162float(ck1[la])
                                + __bfloat162float(sCQ[cl * CQ_W + (la - Lb0)])) * SCALE2;
                    float v3 = (sfr[nb][3] + __bfloat162float(ck1[lb])
                                + __bfloat162float(sCQ[(cl + 1) * CQ_W + (lb - Lb1)])) * SCALE2;
                    if (!(m1v && mc0)) v2 = NEGMAX;
                    if (!(m1v && mc1)) v3 = NEGMAX;
                    sfr[nb][2] = v2; sfr[nb][3] = v3;
                    tmx1 = fmaxf(tmx1, fmaxf(v2, v3));
                }
            }
        }
        tmx0 = fmaxf(tmx0, __shfl_xor_sync(0xffffffffu, tmx0, 1));
        tmx0 = fmaxf(tmx0, __shfl_xor_sync(0xffffffffu, tmx0, 2));
        tmx1 = fmaxf(tmx1, __shfl_xor_sync(0xffffffffu, tmx1, 1));
        tmx1 = fmaxf(tmx1, __shfl_xor_sync(0xffffffffu, tmx1, 2));

        const float mn0 = fmaxf(m0, tmx0), mn1 = fmaxf(m1, tmx1);
        const float sc0 = exp2f(m0 - mn0), sc1 = exp2f(m1 - mn1);
        m0 = mn0; m1 = mn1;
        float rs0 = 0.f, rs1 = 0.f;
        #pragma unroll
        for (int nb = 0; nb < 8; nb++) {
            sfr[nb][0] = exp2f(sfr[nb][0] - mn0);
            sfr[nb][1] = exp2f(sfr[nb][1] - mn0);
            sfr[nb][2] = exp2f(sfr[nb][2] - mn1);
            sfr[nb][3] = exp2f(sfr[nb][3] - mn1);
            rs0 += sfr[nb][0] + sfr[nb][1];
            rs1 += sfr[nb][2] + sfr[nb][3];
        }
        rs0 += __shfl_xor_sync(0xffffffffu, rs0, 1);
        rs0 += __shfl_xor_sync(0xffffffffu, rs0, 2);
        rs1 += __shfl_xor_sync(0xffffffffu, rs1, 1);
        rs1 += __shfl_xor_sync(0xffffffffu, rs1, 2);
        l0 = l0 * sc0 + rs0;
        l1 = l1 * sc1 + rs1;
        #pragma unroll
        for (int df = 0; df < 8; df++) {
            O[df][0] *= sc0; O[df][1] *= sc0;
            O[df][2] *= sc1; O[df][3] *= sc1;
        }

        #pragma unroll
        for (int kk2 = 0; kk2 < 4; kk2++) {
            uint32_t pf[4];
            pf[0] = packbf2(sfr[2 * kk2][0],     sfr[2 * kk2][1]);
            pf[1] = packbf2(sfr[2 * kk2][2],     sfr[2 * kk2][3]);
            pf[2] = packbf2(sfr[2 * kk2 + 1][0], sfr[2 * kk2 + 1][1]);
            pf[3] = packbf2(sfr[2 * kk2 + 1][2], sfr[2 * kk2 + 1][3]);
            #pragma unroll
            for (int dg = 0; dg < 4; dg++) {
                uint32_t r4[4];
                int n   = dg * 16 + ((lane >> 4) << 3) + (lane & 7);
                int c16 = kk2 * 2 + ((lane >> 3) & 1);
                ldsm4(r4, uv + swz128(n, c16));
                mma16816(O[2 * dg],     pf, r4);
                mma16816(O[2 * dg + 1], pf, r4 + 2);
            }
        }
        __syncthreads();
    }

    const size_t base = ((size_t)z * NH + h) * S;
    if ((lane & 3) == 0) {
        ML[base + r0] = make_float2(m0, l0);
        ML[base + r1] = make_float2(m1, l1);
    }
    float* o0 = Opart + (base + r0) * D + (lane & 3) * 2;
    float* o1 = Opart + (base + r1) * D + (lane & 3) * 2;
    #pragma unroll
    for (int df = 0; df < 8; df++) {
        *(float2*)(o0 + df * 8) = make_float2(O[df][0], O[df][1]);
        *(float2*)(o1 + df * 8) = make_float2(O[df][2], O[df][3]);
    }
}

// ---------------------------------------------------------------------------
// Merge the ZSPL split-K slices for a 6-head half -> normalized bf16 context.
// ---------------------------------------------------------------------------
__global__ void __launch_bounds__(256) merge_attn(
    const float* __restrict__ Opart, const float2* __restrict__ ML,
    bf16* __restrict__ CTX, int hbase)
{
    const int p = blockIdx.x * 8 + (threadIdx.x >> 5);
    const int lane = threadIdx.x & 31;
    const int h = hbase + p / S, row = p % S;
    const int q = h * S + row;

    float2 ml[ZSPL];
    float M = NEGMAX;
    #pragma unroll
    for (int zz = 0; zz < ZSPL; zz++) {
        ml[zz] = ML[zz * NH * S + q];
        M = fmaxf(M, ml[zz].x);
    }
    float w[ZSPL], denom = 0.f;
    #pragma unroll
    for (int zz = 0; zz < ZSPL; zz++) {
        w[zz] = exp2f(ml[zz].x - M);
        denom += w[zz] * ml[zz].y;
    }
    const float inv = 1.0f / denom;

    const int d = lane * 2;
    float ax = 0.f, ay = 0.f;
    #pragma unroll
    for (int zz = 0; zz < ZSPL; zz++) {
        const float2 v = *(const float2*)(Opart + ((size_t)zz * NH * S + q) * D + d);
        ax += w[zz] * v.x;
        ay += w[zz] * v.y;
    }
    *(__nv_bfloat162*)(CTX + (long)row * H + h * D + d) =
        __float22bfloat162_rn(make_float2(ax * inv, ay * inv));
}

// ---------------------------------------------------------------------------
__global__ void cvt_bf16_2(const float* __restrict__ x0, bf16* __restrict__ y0, int n0,
                           const float* __restrict__ x1, bf16* __restrict__ y1, int n1)
{
    int i = blockIdx.x * 256 + threadIdx.x;
    if (i < n0) y0[i] = __float2bfloat16(x0[i]);
    else if (i < n0 + n1) y1[i - n0] = __float2bfloat16(x1[i - n0]);
}

struct P6 { const float* p[6]; };
__global__ void wtrans6(P6 srcs, bf16* __restrict__ Wt)
{
    __shared__ float t[32][33];
    const float* W = srcs.p[blockIdx.z];
    bf16* dst = Wt + (size_t)blockIdx.z * H * H;
    const int bx = blockIdx.x * 32, by = blockIdx.y * 32;
    #pragma unroll
    for (int i = threadIdx.y; i < 32; i += 8)
        t[i][threadIdx.x] = W[(long)(by + i) * H + bx + threadIdx.x];
    __syncthreads();
    #pragma unroll
    for (int i = threadIdx.y; i < 32; i += 8)
        dst[(long)(bx + i) * H + by + threadIdx.x] = __float2bfloat16(t[threadIdx.x][i]);
}

__global__ void ln_kernel(const float* __restrict__ x,
                          const float* __restrict__ gamma,
                          const float* __restrict__ beta,
                          float* __restrict__ out)
{
    __shared__ float rs[8], rq[8];
    const int s = blockIdx.x, tid = threadIdx.x;
    const float* row = x + (long)s * H;
    float a0 = row[tid], a1 = row[tid + 256], a2 = row[tid + 512];
    float sum = a0 + a1 + a2;
    float sq  = a0 * a0 + a1 * a1 + a2 * a2;
    #pragma unroll
    for (int o = 16; o > 0; o >>= 1) {
        sum += __shfl_xor_sync(0xffffffffu, sum, o);
        sq  += __shfl_xor_sync(0xffffffffu, sq,  o);
    }
    if ((tid & 31) == 0) { rs[tid >> 5] = sum; rq[tid >> 5] = sq; }
    __syncthreads();
    float ts = 0.f, tq = 0.f;
    #pragma unroll
    for (int w = 0; w < 8; w++) { ts += rs[w]; tq += rq[w]; }
    float mean = ts * (1.0f / H);
    float var  = tq * (1.0f / H) - mean * mean;
    float inv  = rsqrtf(var + 1e-7f);
    float* o = out + (long)s * H;
    o[tid]       = (a0 - mean) * inv * gamma[tid]       + beta[tid];
    o[tid + 256] = (a1 - mean) * inv * gamma[tid + 256] + beta[tid + 256];
    o[tid + 512] = (a2 - mean) * inv * gamma[tid + 512] + beta[tid + 512];
}

// ---------------------------------------------------------------------------
extern "C" void kernel_launch(void* const* d_in, const int* in_sizes, int n_in,
                              void* d_out, int out_size)
{
    const float* hidden = (const float*)d_in[0];
    const int*   mask   = (const int*)  d_in[1];
    const float* Wq     = (const float*)d_in[2];
    const float* bq     = (const float*)d_in[3];
    const float* Wk     = (const float*)d_in[4];
    const float* bk     = (const float*)d_in[5];
    const float* Wv     = (const float*)d_in[6];
    const float* bv     = (const float*)d_in[7];
    const float* rel    = (const float*)d_in[8];
    const float* Wpk    = (const float*)d_in[9];
    const float* Wpq    = (const float*)d_in[10];
    const float* bpq    = (const float*)d_in[11];
    const float* Wo     = (const float*)d_in[12];
    const float* bo     = (const float*)d_in[13];
    const float* gamma  = (const float*)d_in[14];
    const float* beta   = (const float*)d_in[15];
    float* out = (float*)d_out;

    bf16 *hbf, *relbf, *Wt, *Qbf, *Kbf, *Vt, *PKbf, *PQbf, *CKb, *CQb, *CTXbf;
    float *TMP, *Opart;
    float2* ML;
    cudaGetSymbolAddress((void**)&hbf,   g_hbf);
    cudaGetSymbolAddress((void**)&relbf, g_relbf);
    cudaGetSymbolAddress((void**)&Wt,    g_Wt);
    cudaGetSymbolAddress((void**)&Qbf,   g_Qbf);
    cudaGetSymbolAddress((void**)&Kbf,   g_Kbf);
    cudaGetSymbolAddress((void**)&Vt,    g_Vt);
    cudaGetSymbolAddress((void**)&PKbf,  g_PKbf);
    cudaGetSymbolAddress((void**)&PQbf,  g_PQbf);
    cudaGetSymbolAddress((void**)&CKb,   g_CKb);
    cudaGetSymbolAddress((void**)&CQb,   g_CQb);
    cudaGetSymbolAddress((void**)&Opart, g_Opart);
    cudaGetSymbolAddress((void**)&ML,    g_ML);
    cudaGetSymbolAddress((void**)&CTXbf, g_CTXbf);
    cudaGetSymbolAddress((void**)&TMP,   g_TMP);

    static cudaStream_t s1 = nullptr, s2 = nullptr;
    static cudaEvent_t evR = nullptr, evP = nullptr, evV = nullptr,
                       evM1 = nullptr, evM2 = nullptr, evW = nullptr;
    static bool init_done = false;
    if (!init_done) {
        cudaFuncSetAttribute(flash_attn,
                             cudaFuncAttributeMaxDynamicSharedMemorySize, FL_SMEM);
        cudaStreamCreateWithFlags(&s1, cudaStreamNonBlocking);
        cudaStreamCreateWithFlags(&s2, cudaStreamNonBlocking);
        cudaEventCreateWithFlags(&evR,  cudaEventDisableTiming);
        cudaEventCreateWithFlags(&evP,  cudaEventDisableTiming);
        cudaEventCreateWithFlags(&evV,  cudaEventDisableTiming);
        cudaEventCreateWithFlags(&evM1, cudaEventDisableTiming);
        cudaEventCreateWithFlags(&evM2, cudaEventDisableTiming);
        cudaEventCreateWithFlags(&evW,  cudaEventDisableTiming);
        init_done = true;
    }

    // --- legal fork: root event on capture-origin stream BEFORE side work ---
    cudaEventRecord(evR, 0);
    cudaStreamWaitEvent(s1, evR, 0);

    // front: cvt (default) || wtrans (s1)
    cvt_bf16_2<<<(S * H + LPOS * H + 255) / 256, 256>>>(
        hidden, hbf, S * H, rel, relbf, LPOS * H);
    P6 w6; w6.p[0] = Wq; w6.p[1] = Wk; w6.p[2] = Wv;
    w6.p[3] = Wpk; w6.p[4] = Wpq; w6.p[5] = Wo;
    wtrans6<<<dim3(H/32, H/32, 6), dim3(32, 8), 0, s1>>>(w6, Wt);
    cudaEventRecord(evW, s1);
    cudaStreamWaitEvent(0, evW, 0);

    // --- projections needed by tables (Q, K, PK, PQ): 288 CTAs ---
    ProjJobs J;
    J.A[0] = hbf;   J.Bw[0] = Wt + 0 * H * H; J.C[0] = Qbf;  J.bias[0] = bq;      J.mode[0] = 0;
    J.A[1] = hbf;   J.Bw[1] = Wt + 1 * H * H; J.C[1] = Kbf;  J.bias[1] = bk;      J.mode[1] = 0;
    J.A[2] = relbf; J.Bw[2] = Wt + 3 * H * H; J.C[2] = PKbf; J.bias[2] = nullptr; J.mode[2] = 0;
    J.A[3] = relbf; J.Bw[3] = Wt + 4 * H * H; J.C[3] = PQbf; J.bias[3] = bpq;     J.mode[3] = 0;
    J.A[4] = nullptr; J.Bw[4] = nullptr; J.C[4] = nullptr; J.bias[4] = nullptr; J.mode[4] = 0;
    J.start[0] = 0;   J.start[1] = 96;  J.start[2] = 192;
    J.start[3] = 240; J.start[4] = 288; J.start[5] = 288;
    gemm_proj<<<288, 256>>>(J);
    cudaEventRecord(evP, 0);

    // --- V projection (96 CTAs) on default stream, concurrent with tables ---
    ProjJobs JV;
    JV.A[0] = hbf; JV.Bw[0] = Wt + 2 * H * H; JV.C[0] = Vt; JV.bias[0] = bv; JV.mode[0] = 1;
    JV.A[1] = nullptr; JV.Bw[1] = nullptr; JV.C[1] = nullptr; JV.bias[1] = nullptr; JV.mode[1] = 0;
    JV.A[2] = JV.A[3] = JV.A[4] = nullptr;
    JV.Bw[2] = JV.Bw[3] = JV.Bw[4] = nullptr;
    JV.C[2] = JV.C[3] = JV.C[4] = nullptr;
    JV.bias[2] = JV.bias[3] = JV.bias[4] = nullptr;
    JV.mode[2] = JV.mode[3] = JV.mode[4] = 0;
    JV.start[0] = 0; JV.start[1] = 96; JV.start[2] = 96;
    JV.start[3] = 96; JV.start[4] = 96; JV.start[5] = 96;
    gemm_proj<<<96, 256>>>(JV);
    cudaEventRecord(evV, 0);

    // --- fork: tables (waits Q/K/PK/PQ) then flash (also waits V) ---
    cudaStreamWaitEvent(s1, evP, 0);
    gemm_tables<<<dim3(LPOS/128, S/128, 12), 256, 0, s1>>>(
        Qbf, Kbf, PKbf, PQbf, CKb, CQb, 0);
    cudaStreamWaitEvent(s2, evP, 0);
    gemm_tables<<<dim3(LPOS/128, S/128, 12), 256, 0, s2>>>(
        Qbf, Kbf, PKbf, PQbf, CKb, CQb, 6);

    cudaStreamWaitEvent(s1, evV, 0);
    flash_attn<<<dim3(S/128, NH/2, ZSPL), 256, FL_SMEM, s1>>>(
        Qbf, Kbf, Vt, CKb, CQb, mask, Opart, ML, 0);
    merge_attn<<<6 * S / 8, 256, 0, s1>>>(Opart, ML, CTXbf, 0);
    cudaEventRecord(evM1, s1);

    cudaStreamWaitEvent(s2, evV, 0);
    flash_attn<<<dim3(S/128, NH/2, ZSPL), 256, FL_SMEM, s2>>>(
        Qbf, Kbf, Vt, CKb, CQb, mask, Opart, ML, 6);
    merge_attn<<<6 * S / 8, 256, 0, s2>>>(Opart, ML, CTXbf, 6);
    cudaEventRecord(evM2, s2);

    // --- join back to default stream ---
    cudaStreamWaitEvent(0, evM1, 0);
    cudaStreamWaitEvent(0, evM2, 0);

    // --- output projection + bias + residual ---
    gemm_out<<<dim3(6, 16), 256>>>(CTXbf, Wt + 5 * H * H, TMP, bo, hidden);

    // --- layernorm ---
    ln_kernel<<<S, 256>>>(TMP, gamma, beta, out);
}